// round 6
// baseline (speedup 1.0000x reference)
#include <cuda_runtime.h>

// ImageRotator — one (angle, image, 32x32 tile) per block.
// img: (32, 1, 512, 512) fp32   angles: (8,) fp32 (degrees)
// out: (32, 8, 512, 512) fp32
//
// R4 pipelined 32 images per block and was barrier/latency bound at 35% occ.
// Here each block does a single image tile: fill 48x48 smem bbox (coalesced),
// one barrier, bilinear gather from smem, float4 store. Latency is hidden by
// 65536 independent blocks instead of an in-block pipeline.

#define IMG_H 512
#define IMG_W 512
#define N_IMG 32
#define N_ANG 8
#define HW (IMG_H * IMG_W)
#define TILE 32
#define BB 48           // bbox: 31*(|c|+|s|) <= 43.9, +2 taps +1 ULP margin
#define BSTR 49         // padded row stride (odd -> spreads banks)
#define LPT 9           // 48*48 / 256 loads per thread

__global__ __launch_bounds__(256, 4) void rotate_one(
    const float* __restrict__ img,
    const float* __restrict__ angles,
    float* __restrict__ out)
{
    __shared__ float sbuf[BB * BSTR];

    const int z   = blockIdx.z;
    const int a   = z >> 5;          // angle
    const int n   = z & 31;          // image
    const int tx0 = blockIdx.x * TILE;
    const int ty0 = blockIdx.y * TILE;

    const float ang = angles[a] * 0.017453292519943295f;
    float sa, ca;
    sincosf(ang, &sa, &ca);          // sin FIRST
    const float cx = (IMG_W - 1) * 0.5f;
    const float cy = (IMG_H - 1) * 0.5f;

    // Source bbox via the SAME fmaf expression as the per-pixel path (corner
    // extrema bound interior samples); -1 margin for ULP safety.
    const float Xa = (float)tx0 - cx,  Xb = (float)(tx0 + TILE - 1) - cx;
    const float Ya = (float)ty0 - cy,  Yb = (float)(ty0 + TILE - 1) - cy;
    float sxa0 = fmaf(ca, Xa, fmaf(-sa, Ya, cx));
    float sxa1 = fmaf(ca, Xb, fmaf(-sa, Ya, cx));
    float sxa2 = fmaf(ca, Xa, fmaf(-sa, Yb, cx));
    float sxa3 = fmaf(ca, Xb, fmaf(-sa, Yb, cx));
    float sya0 = fmaf(sa, Xa, fmaf(ca, Ya, cy));
    float sya1 = fmaf(sa, Xb, fmaf(ca, Ya, cy));
    float sya2 = fmaf(sa, Xa, fmaf(ca, Yb, cy));
    float sya3 = fmaf(sa, Xb, fmaf(ca, Yb, cy));
    const int bx0 = (int)floorf(fminf(fminf(sxa0, sxa1), fminf(sxa2, sxa3))) - 1;
    const int by0 = (int)floorf(fminf(fminf(sya0, sya1), fminf(sya2, sya3))) - 1;

    const int tid = threadIdx.x;

    // ---- fill smem bbox (coalesced; clamped border duplication is harmless,
    //      those texels are only read with weight 0) ----
    const float* ip = img + (size_t)n * HW;
#pragma unroll
    for (int k = 0; k < LPT; k++) {
        int i = tid + k * 256;               // 0..2303
        int r = i / BB;
        int c = i - r * BB;
        int gy = min(max(by0 + r, 0), IMG_H - 1);
        int gx = min(max(bx0 + c, 0), IMG_W - 1);
        sbuf[r * BSTR + c] = __ldg(ip + gy * IMG_W + gx);
    }
    __syncthreads();

    // ---- gather: each thread owns 4 consecutive x of one row ----
    const int orow = tid >> 3;               // 0..31
    const int ocol = (tid & 7) << 2;         // 0,4,...,28
    const int oy   = ty0 + orow;
    const float Yf = (float)oy - cy;

    float acc[4];
#pragma unroll
    for (int j = 0; j < 4; j++) {
        int ox = tx0 + ocol + j;
        float Xf = (float)ox - cx;
        float sx = fmaf(ca, Xf, fmaf(-sa, Yf, cx));
        float sy = fmaf(sa, Xf, fmaf(ca, Yf, cy));
        float x0f = floorf(sx), y0f = floorf(sy);
        float wx = sx - x0f,   wy = sy - y0f;
        int x0 = (int)x0f, y0 = (int)y0f;
        int x1 = x0 + 1,   y1 = y0 + 1;
        bool vx0 = (x0 >= 0) & (x0 < IMG_W);
        bool vx1 = (x1 >= 0) & (x1 < IMG_W);
        bool vy0 = (y0 >= 0) & (y0 < IMG_H);
        bool vy1 = (y1 >= 0) & (y1 < IMG_H);
        int xc0 = min(max(x0, 0), IMG_W - 1), xc1 = min(max(x1, 0), IMG_W - 1);
        int yc0 = min(max(y0, 0), IMG_H - 1), yc1 = min(max(y1, 0), IMG_H - 1);
        float omwx = 1.0f - wx, omwy = 1.0f - wy;
        float w00 = (vy0 && vx0) ? (omwy * omwx) : 0.0f;
        float w01 = (vy0 && vx1) ? (omwy * wx)   : 0.0f;
        float w10 = (vy1 && vx0) ? (wy * omwx)   : 0.0f;
        float w11 = (vy1 && vx1) ? (wy * wx)     : 0.0f;

        // local smem indices, hard-clamped into the buffer
        int xi0 = min(max(xc0 - bx0, 0), BB - 1), xi1 = min(max(xc1 - bx0, 0), BB - 1);
        int yi0 = min(max(yc0 - by0, 0), BB - 1), yi1 = min(max(yc1 - by0, 0), BB - 1);

        float v00 = sbuf[yi0 * BSTR + xi0];
        float v01 = sbuf[yi0 * BSTR + xi1];
        float v10 = sbuf[yi1 * BSTR + xi0];
        float v11 = sbuf[yi1 * BSTR + xi1];
        acc[j] = fmaf(v00, w00, fmaf(v01, w01, fmaf(v10, w10, v11 * w11)));
    }

    float* op = out + ((size_t)n * N_ANG + a) * (size_t)HW
                    + (size_t)oy * IMG_W + (tx0 + ocol);
    *(float4*)op = make_float4(acc[0], acc[1], acc[2], acc[3]);
}

extern "C" void kernel_launch(void* const* d_in, const int* in_sizes, int n_in,
                              void* d_out, int out_size) {
    const float* img;
    const float* angles;
    if (in_sizes[0] > in_sizes[1]) {
        img    = (const float*)d_in[0];
        angles = (const float*)d_in[1];
    } else {
        angles = (const float*)d_in[0];
        img    = (const float*)d_in[1];
    }
    float* out = (float*)d_out;

    dim3 grid(IMG_W / TILE, IMG_H / TILE, N_ANG * N_IMG);  // (16,16,256)
    rotate_one<<<grid, 256>>>(img, angles, out);
}

// round 7
// speedup vs baseline: 1.7144x; 1.7144x over previous
#include <cuda_runtime.h>

// ImageRotator — (angle, 8-image group, 32x32 tile) per block.
// img: (32, 1, 512, 512) fp32   angles: (8,) fp32 (degrees)
// out: (32, 8, 512, 512) fp32
//
// R4 (32 img/block): amortized precompute but 76 regs -> 3 blocks/SM, 32-deep
// barrier chain -> latency-bound @205us. R5 (1 img/block): occupancy fine but
// precompute x32 -> alu 73.5% @281us. This round: group of 8 images, one
// n-invariant precompute, double-buffered smem, register diet (single packed
// tap offset per output) for >=4 blocks/SM.

#define IMG_H 512
#define IMG_W 512
#define N_IMG 32
#define N_ANG 8
#define HW (IMG_H * IMG_W)
#define TILE 32
#define GRP 8            // images per block
#define BB 48            // bbox: 31*(|c|+|s|) <= 43.9, +2 taps +1 ULP margin
#define BSTR 49          // odd padded row stride -> conflict-free column walks
#define LPT 9            // 48*48 / 256

__global__ __launch_bounds__(256, 4) void rotate_grp(
    const float* __restrict__ img,
    const float* __restrict__ angles,
    float* __restrict__ out)
{
    __shared__ float sbuf[2][BB * BSTR];

    const int z    = blockIdx.z;          // 0..31
    const int a    = z >> 2;              // angle 0..7
    const int n0   = (z & 3) * GRP;       // first image of group
    const int tx0  = blockIdx.x * TILE;
    const int ty0  = blockIdx.y * TILE;

    const float ang = angles[a] * 0.017453292519943295f;
    float sa, ca;
    sincosf(ang, &sa, &ca);               // sin FIRST
    const float cx = (IMG_W - 1) * 0.5f;
    const float cy = (IMG_H - 1) * 0.5f;

    // Source bbox via the SAME fmaf expression as the per-pixel path, -1 margin.
    const float Xa = (float)tx0 - cx,  Xb = (float)(tx0 + TILE - 1) - cx;
    const float Ya = (float)ty0 - cy,  Yb = (float)(ty0 + TILE - 1) - cy;
    float sxa0 = fmaf(ca, Xa, fmaf(-sa, Ya, cx));
    float sxa1 = fmaf(ca, Xb, fmaf(-sa, Ya, cx));
    float sxa2 = fmaf(ca, Xa, fmaf(-sa, Yb, cx));
    float sxa3 = fmaf(ca, Xb, fmaf(-sa, Yb, cx));
    float sya0 = fmaf(sa, Xa, fmaf(ca, Ya, cy));
    float sya1 = fmaf(sa, Xb, fmaf(ca, Ya, cy));
    float sya2 = fmaf(sa, Xa, fmaf(ca, Yb, cy));
    float sya3 = fmaf(sa, Xb, fmaf(ca, Yb, cy));
    const int bx0 = (int)floorf(fminf(fminf(sxa0, sxa1), fminf(sxa2, sxa3))) - 1;
    const int by0 = (int)floorf(fminf(fminf(sya0, sya1), fminf(sya2, sya3))) - 1;

    const int tid = threadIdx.x;

    // ---- n-invariant fill addresses (coalesced: lanes contiguous in c) ----
    int laddr[LPT], lidx[LPT];
#pragma unroll
    for (int k = 0; k < LPT; k++) {
        int i = tid + k * 256;            // 0..2303
        int r = i / BB;
        int c = i - r * BB;
        int gy = min(max(by0 + r, 0), IMG_H - 1);
        int gx = min(max(bx0 + c, 0), IMG_W - 1);
        laddr[k] = gy * IMG_W + gx;
        lidx[k]  = r * BSTR + c;
    }

    // ---- n-invariant gather state: 1 offset + 4 weights per output ----
    const int orow = tid >> 3;            // 0..31
    const int ocol = (tid & 7) << 2;      // 0,4,...,28
    const int oy   = ty0 + orow;
    const float Yf = (float)oy - cy;

    int   offs[4];
    float wts[4][4];
#pragma unroll
    for (int j = 0; j < 4; j++) {
        int ox = tx0 + ocol + j;
        float Xf = (float)ox - cx;
        float sx = fmaf(ca, Xf, fmaf(-sa, Yf, cx));
        float sy = fmaf(sa, Xf, fmaf(ca, Yf, cy));
        float x0f = floorf(sx), y0f = floorf(sy);
        float wx = sx - x0f,   wy = sy - y0f;
        int x0 = (int)x0f, y0 = (int)y0f;
        bool vx0 = (x0 >= 0) & (x0 < IMG_W);
        bool vx1 = (x0 >= -1) & (x0 < IMG_W - 1);
        bool vy0 = (y0 >= 0) & (y0 < IMG_H);
        bool vy1 = (y0 >= -1) & (y0 < IMG_H - 1);
        float omwx = 1.0f - wx, omwy = 1.0f - wy;
        wts[j][0] = (vy0 && vx0) ? (omwy * omwx) : 0.0f;
        wts[j][1] = (vy0 && vx1) ? (omwy * wx)   : 0.0f;
        wts[j][2] = (vy1 && vx0) ? (wy * omwx)   : 0.0f;
        wts[j][3] = (vy1 && vx1) ? (wy * wx)     : 0.0f;
        // single packed base offset; taps = o, o+1, o+BSTR, o+BSTR+1.
        // clamp to [0, BB-2]: never binds for nonzero-weight taps (bbox has a
        // 1px margin), keeps all 4 reads inside the buffer for weight-0 taps.
        int xi0 = min(max(x0 - bx0, 0), BB - 2);
        int yi0 = min(max(y0 - by0, 0), BB - 2);
        offs[j] = yi0 * BSTR + xi0;
    }

    // ---- prologue: fill buffer 0 with image n0 ----
    const float* ip0 = img + (size_t)n0 * HW;
#pragma unroll
    for (int k = 0; k < LPT; k++)
        sbuf[0][lidx[k]] = __ldg(ip0 + laddr[k]);
    __syncthreads();

    float* op = out + ((size_t)n0 * N_ANG + a) * (size_t)HW
                    + (size_t)oy * IMG_W + (tx0 + ocol);

    for (int n = 0; n < GRP; n++) {
        const float* sb = sbuf[n & 1];
        if (n + 1 < GRP) {
            const float* ipn = img + (size_t)(n0 + n + 1) * HW;
            float* db = sbuf[(n + 1) & 1];
#pragma unroll
            for (int k = 0; k < LPT; k++)
                db[lidx[k]] = __ldg(ipn + laddr[k]);
        }

        float acc[4];
#pragma unroll
        for (int j = 0; j < 4; j++) {
            int o = offs[j];
            float v00 = sb[o];
            float v01 = sb[o + 1];
            float v10 = sb[o + BSTR];
            float v11 = sb[o + BSTR + 1];
            acc[j] = fmaf(v00, wts[j][0],
                     fmaf(v01, wts[j][1],
                     fmaf(v10, wts[j][2], v11 * wts[j][3])));
        }
        *(float4*)op = make_float4(acc[0], acc[1], acc[2], acc[3]);
        op += (size_t)N_ANG * HW;

        __syncthreads();
    }
}

extern "C" void kernel_launch(void* const* d_in, const int* in_sizes, int n_in,
                              void* d_out, int out_size) {
    const float* img;
    const float* angles;
    if (in_sizes[0] > in_sizes[1]) {
        img    = (const float*)d_in[0];
        angles = (const float*)d_in[1];
    } else {
        angles = (const float*)d_in[0];
        img    = (const float*)d_in[1];
    }
    float* out = (float*)d_out;

    dim3 grid(IMG_W / TILE, IMG_H / TILE, N_ANG * (N_IMG / GRP));  // (16,16,32)
    rotate_grp<<<grid, 256>>>(img, angles, out);
}